// round 8
// baseline (speedup 1.0000x reference)
#include <cuda_runtime.h>
#include <cuda_bf16.h>
#include <math.h>

#define BB 2
#define SS 2048
#define HH 16
#define DHD 128
#define HIDD 2048
#define NQKV 6144   // (H + 2*HKV) * DH

// ---------------- scratch (static device allocations — allowed) ----------------
__device__ float g_qkv[(size_t)BB * SS * NQKV];         // [4096, 6144]
__device__ float g_q[(size_t)BB * HH * SS * DHD];       // [bh, s, d] (pre-scaled by 1/sqrt(DH))
__device__ float g_k[(size_t)BB * HH * SS * DHD];
__device__ float g_v[(size_t)BB * HH * SS * DHD];
__device__ float g_attn[(size_t)BB * SS * HH * DHD];    // [b, s, h, d] == [4096, 2048]
__device__ float g_hid_r[(size_t)BB * SS * HIDD];       // RNA-tf32-rounded copies
__device__ float g_wqkv_r[(size_t)NQKV * HIDD];
__device__ float g_wo_r[(size_t)HIDD * HIDD];

// ---------------- helpers ----------------
__device__ __forceinline__ unsigned f2tf(float f) {
    unsigned u;
    asm("cvt.rna.tf32.f32 %0, %1;" : "=r"(u) : "f"(f));
    return u;
}

__device__ __forceinline__ unsigned smem_u32(const void* p) {
    unsigned a;
    asm("{ .reg .u64 t; cvta.to.shared.u64 t, %1; cvt.u32.u64 %0, t; }" : "=r"(a) : "l"(p));
    return a;
}

__device__ __forceinline__ void cp16(unsigned dst, const void* src) {
    asm volatile("cp.async.cg.shared.global [%0], [%1], 16;\n" :: "r"(dst), "l"(src));
}

__device__ __forceinline__ void mma_tf32(float (&c)[4],
                                         unsigned a0, unsigned a1, unsigned a2, unsigned a3,
                                         unsigned b0, unsigned b1) {
    asm volatile(
        "mma.sync.aligned.m16n8k8.row.col.f32.tf32.tf32.f32 "
        "{%0,%1,%2,%3},{%4,%5,%6,%7},{%8,%9},{%0,%1,%2,%3};\n"
        : "+f"(c[0]), "+f"(c[1]), "+f"(c[2]), "+f"(c[3])
        : "r"(a0), "r"(a1), "r"(a2), "r"(a3), "r"(b0), "r"(b1));
}

// ---------------- GEMM: C[M,N] = A[M,K] * B[N,K]^T (both row-major, K-contig) ------------
// Block 128x128, 8 warps (2x4), warp tile 64x32, BK=16, 256 threads, 2 CTAs/SM
// (=16 warps/SM to hide LDS->MMA latency; acc=64 regs so the 128-reg cap holds).
// 4-stage cp.async.cg pipeline (prefetch distance 3), natural k-order smem with
// row stride 20 words: banks (20g+tg)%32 cover all 32 banks => conflict-free LDS.32.
// Inputs MUST be pre-rounded to RNA-tf32 (f32 bit pattern == tf32 operand format).
#define NSTG 4
#define SRD 20
#define STW (256 * SRD)                    // words per stage (A 128 rows + B 128 rows)
#define GEMM_SMEM (NSTG * STW * 4)         // 81920 bytes

__global__ __launch_bounds__(256, 2) void gemm_nt(const float* __restrict__ A,
                                                  const float* __restrict__ Bm,
                                                  float* __restrict__ C,
                                                  int M, int N, int K) {
    extern __shared__ float sm[];
    const unsigned smb = smem_u32(sm);
    const int tid = threadIdx.x;
    const int lane = tid & 31;
    const int w = tid >> 5;
    const int g = lane >> 2;
    const int tg = lane & 3;
    const int wrow = (w >> 2) * 64;
    const int wcol = (w & 3) * 32;
    const int bm = blockIdx.y * 128;
    const int bn = blockIdx.x * 128;
    const int nk = K >> 4;

    float acc[4][4][4];
#pragma unroll
    for (int i = 0; i < 4; i++)
#pragma unroll
        for (int j = 0; j < 4; j++)
#pragma unroll
            for (int l = 0; l < 4; l++) acc[i][j][l] = 0.f;

    // loader: 512 A-chunks + 512 B-chunks of 16B per ktile, 4 per thread
    const int lr = tid >> 1;            // row 0..127
    const int lc = (tid & 1) * 2;       // chunk pair 0 or 2

#define FILL(slot, ktv)                                                                    \
    {                                                                                      \
        const unsigned stA = smb + (slot) * (STW * 4);                                     \
        const unsigned stB = stA + 128 * SRD * 4;                                          \
        const int kof = (ktv) * 16 + lc * 4;                                               \
        cp16(stA + (lr * SRD + lc * 4) * 4, A + (size_t)(bm + lr) * K + kof);              \
        cp16(stA + (lr * SRD + lc * 4 + 4) * 4, A + (size_t)(bm + lr) * K + kof + 4);      \
        cp16(stB + (lr * SRD + lc * 4) * 4, Bm + (size_t)(bn + lr) * K + kof);             \
        cp16(stB + (lr * SRD + lc * 4 + 4) * 4, Bm + (size_t)(bn + lr) * K + kof + 4);     \
        asm volatile("cp.async.commit_group;" ::: "memory");                               \
    }

    FILL(0, 0)
    FILL(1, 1)
    FILL(2, 2)

    for (int kt = 0; kt < nk; kt++) {
        asm volatile("cp.async.wait_group 2;" ::: "memory");
        __syncthreads();
        // prefetch stage kt+3 into slot (kt-1)&3 (fully consumed by all warps pre-sync)
        const int pf = kt + 3;
        if (pf < nk) {
            FILL(pf & 3, pf)
        } else {
            asm volatile("cp.async.commit_group;" ::: "memory");  // keep group count aligned
        }

        const float* sa = sm + (kt & 3) * STW;
        const float* sb = sa + 128 * SRD;
#pragma unroll
        for (int ks = 0; ks < 2; ks++) {
            const int ko = ks * 8 + tg;
            unsigned bfr[4][2];
#pragma unroll
            for (int nt = 0; nt < 4; nt++) {
                int rn = wcol + nt * 8 + g;
                bfr[nt][0] = __float_as_uint(sb[rn * SRD + ko]);
                bfr[nt][1] = __float_as_uint(sb[rn * SRD + ko + 4]);
            }
#pragma unroll
            for (int mt = 0; mt < 4; mt++) {
                int r0 = wrow + mt * 16 + g;
                unsigned a0 = __float_as_uint(sa[r0 * SRD + ko]);
                unsigned a1 = __float_as_uint(sa[(r0 + 8) * SRD + ko]);
                unsigned a2 = __float_as_uint(sa[r0 * SRD + ko + 4]);
                unsigned a3 = __float_as_uint(sa[(r0 + 8) * SRD + ko + 4]);
#pragma unroll
                for (int nt = 0; nt < 4; nt++)
                    mma_tf32(acc[mt][nt], a0, a1, a2, a3, bfr[nt][0], bfr[nt][1]);
            }
        }
    }

#pragma unroll
    for (int mt = 0; mt < 4; mt++) {
        int rr = bm + wrow + mt * 16 + g;
#pragma unroll
        for (int nt = 0; nt < 4; nt++) {
            int cc = bn + wcol + nt * 8 + 2 * tg;
            *(float2*)&C[(size_t)rr * N + cc] = make_float2(acc[mt][nt][0], acc[mt][nt][1]);
            *(float2*)&C[(size_t)(rr + 8) * N + cc] = make_float2(acc[mt][nt][2], acc[mt][nt][3]);
        }
    }
#undef FILL
}

// ---------------- RNA-tf32 pre-round (elementwise) ----------------
__global__ void round_tf32_kernel(const float4* __restrict__ in, float4* __restrict__ out) {
    int i = blockIdx.x * blockDim.x + threadIdx.x;
    float4 v = in[i];
    v.x = __uint_as_float(f2tf(v.x));
    v.y = __uint_as_float(f2tf(v.y));
    v.z = __uint_as_float(f2tf(v.z));
    v.w = __uint_as_float(f2tf(v.w));
    out[i] = v;
}

// ---------------- RoPE + split + transpose to head-major ----------------
__global__ void rope_split_kernel(const float* __restrict__ cosb, const float* __restrict__ sinb) {
    int idx = blockIdx.x * blockDim.x + threadIdx.x;  // pair index, exact grid
    int m = idx / 3072;
    int p = idx - m * 3072;
    int o = p * 2;
    int head = o >> 7;
    int d = o & 127;
    int b = m >> 11;
    int s = m & 2047;
    float2 x = *(const float2*)(g_qkv + (size_t)m * NQKV + o);
    if (head < 2 * HH) {
        float c = cosb[s * DHD + d];
        float sn = sinb[s * DHD + d];
        float y0 = x.x * c - x.y * sn;
        float y1 = x.y * c + x.x * sn;
        if (head < HH) {
            const float sc = 0.08838834764831845f;  // 1/sqrt(128)
            float* dst = g_q + (((size_t)(b * HH + head)) * SS + s) * DHD + d;
            *(float2*)dst = make_float2(y0 * sc, y1 * sc);
        } else {
            float* dst = g_k + (((size_t)(b * HH + head - HH)) * SS + s) * DHD + d;
            *(float2*)dst = make_float2(y0, y1);
        }
    } else {
        float* dst = g_v + (((size_t)(b * HH + head - 2 * HH)) * SS + s) * DHD + d;
        *(float2*)dst = x;
    }
}

// ---------------- Flash attention (legacy mma path) ----------------
// Grid: (S/128, B*H). 256 threads = 8 warps, each warp owns 16 q-rows.
#define FA_SMEM_BYTES 171008

__global__ __launch_bounds__(256, 1) void flash_kernel() {
    extern __shared__ unsigned fsm[];
    unsigned* sQ = fsm;                // 128*132 = 16896
    unsigned* sK = fsm + 16896;        // 64*132  =  8448
    unsigned* sV = fsm + 25344;        // 64*136  =  8704
    unsigned* sP = fsm + 34048;        // 128*68  =  8704

    const int tid = threadIdx.x;
    const int lane = tid & 31;
    const int w = tid >> 5;
    const int g = lane >> 2;
    const int tg = lane & 3;
    const int qt = blockIdx.x;
    const int bh = blockIdx.y;
    const int qrow = w * 16;

    const float* qp = g_q + ((size_t)bh * SS + qt * 128) * DHD;
#pragma unroll
    for (int i = 0; i < 16; i++) {
        int id = tid + 256 * i;
        int r = id >> 5, c4 = (id & 31) * 4;
        float4 v = *(const float4*)(qp + (size_t)r * DHD + c4);
        unsigned* d = sQ + r * 132 + c4;
        d[0] = f2tf(v.x); d[1] = f2tf(v.y); d[2] = f2tf(v.z); d[3] = f2tf(v.w);
    }

    float m0 = -1e30f, m1 = -1e30f, l0 = 0.f, l1 = 0.f;
    float oacc[16][4];
#pragma unroll
    for (int nt = 0; nt < 16; nt++) { oacc[nt][0] = 0; oacc[nt][1] = 0; oacc[nt][2] = 0; oacc[nt][3] = 0; }

    for (int kt = 0; kt < SS / 64; kt++) {
        const float* kp = g_k + ((size_t)bh * SS + kt * 64) * DHD;
        const float* vp = g_v + ((size_t)bh * SS + kt * 64) * DHD;
#pragma unroll
        for (int i = 0; i < 8; i++) {
            int id = tid + 256 * i;
            int r = id >> 5, c4 = (id & 31) * 4;
            float4 kv = *(const float4*)(kp + (size_t)r * DHD + c4);
            unsigned* dk = sK + r * 132 + c4;
            dk[0] = f2tf(kv.x); dk[1] = f2tf(kv.y); dk[2] = f2tf(kv.z); dk[3] = f2tf(kv.w);
            float4 vv = *(const float4*)(vp + (size_t)r * DHD + c4);
            unsigned* dv = sV + r * 136 + c4;
            dv[0] = f2tf(vv.x); dv[1] = f2tf(vv.y); dv[2] = f2tf(vv.z); dv[3] = f2tf(vv.w);
        }
        __syncthreads();

        // S = Q K^T  (scale already folded into Q)
        float sacc[8][4];
#pragma unroll
        for (int nt = 0; nt < 8; nt++) { sacc[nt][0] = 0; sacc[nt][1] = 0; sacc[nt][2] = 0; sacc[nt][3] = 0; }
#pragma unroll
        for (int ks = 0; ks < 16; ks++) {
            unsigned a0 = sQ[(qrow + g) * 132 + ks * 8 + tg];
            unsigned a1 = sQ[(qrow + g + 8) * 132 + ks * 8 + tg];
            unsigned a2 = sQ[(qrow + g) * 132 + ks * 8 + tg + 4];
            unsigned a3 = sQ[(qrow + g + 8) * 132 + ks * 8 + tg + 4];
#pragma unroll
            for (int nt = 0; nt < 8; nt++) {
                unsigned b0 = sK[(nt * 8 + g) * 132 + ks * 8 + tg];
                unsigned b1 = sK[(nt * 8 + g) * 132 + ks * 8 + tg + 4];
                mma_tf32(sacc[nt], a0, a1, a2, a3, b0, b1);
            }
        }

        // online softmax (rows g and g+8 of this warp's 16)
        float mx0 = sacc[0][0], mx1 = sacc[0][2];
#pragma unroll
        for (int nt = 0; nt < 8; nt++) {
            mx0 = fmaxf(mx0, fmaxf(sacc[nt][0], sacc[nt][1]));
            mx1 = fmaxf(mx1, fmaxf(sacc[nt][2], sacc[nt][3]));
        }
        mx0 = fmaxf(mx0, __shfl_xor_sync(0xffffffffu, mx0, 1));
        mx0 = fmaxf(mx0, __shfl_xor_sync(0xffffffffu, mx0, 2));
        mx1 = fmaxf(mx1, __shfl_xor_sync(0xffffffffu, mx1, 1));
        mx1 = fmaxf(mx1, __shfl_xor_sync(0xffffffffu, mx1, 2));
        float nm0 = fmaxf(m0, mx0), nm1 = fmaxf(m1, mx1);
        float al0 = __expf(m0 - nm0), al1 = __expf(m1 - nm1);
        float sum0 = 0.f, sum1 = 0.f;
        unsigned* pr0 = sP + (qrow + g) * 68;
        unsigned* pr1 = sP + (qrow + g + 8) * 68;
#pragma unroll
        for (int nt = 0; nt < 8; nt++) {
            int cc = nt * 8 + 2 * tg;
            unsigned u00 = f2tf(__expf(sacc[nt][0] - nm0));
            unsigned u01 = f2tf(__expf(sacc[nt][1] - nm0));
            unsigned u10 = f2tf(__expf(sacc[nt][2] - nm1));
            unsigned u11 = f2tf(__expf(sacc[nt][3] - nm1));
            sum0 += __uint_as_float(u00) + __uint_as_float(u01);  // sum the tf32-rounded P
            sum1 += __uint_as_float(u10) + __uint_as_float(u11);
            pr0[cc] = u00; pr0[cc + 1] = u01;
            pr1[cc] = u10; pr1[cc + 1] = u11;
        }
        sum0 += __shfl_xor_sync(0xffffffffu, sum0, 1);
        sum0 += __shfl_xor_sync(0xffffffffu, sum0, 2);
        sum1 += __shfl_xor_sync(0xffffffffu, sum1, 1);
        sum1 += __shfl_xor_sync(0xffffffffu, sum1, 2);
        l0 = l0 * al0 + sum0;
        l1 = l1 * al1 + sum1;
        m0 = nm0; m1 = nm1;
#pragma unroll
        for (int nt = 0; nt < 16; nt++) {
            oacc[nt][0] *= al0; oacc[nt][1] *= al0;
            oacc[nt][2] *= al1; oacc[nt][3] *= al1;
        }
        __syncwarp();

        // O += P V   (P is A-operand via smem, V is B-operand)
#pragma unroll
        for (int ks = 0; ks < 8; ks++) {
            unsigned a0 = sP[(qrow + g) * 68 + ks * 8 + tg];
            unsigned a1 = sP[(qrow + g + 8) * 68 + ks * 8 + tg];
            unsigned a2 = sP[(qrow + g) * 68 + ks * 8 + tg + 4];
            unsigned a3 = sP[(qrow + g + 8) * 68 + ks * 8 + tg + 4];
#pragma unroll
            for (int nt = 0; nt < 16; nt++) {
                unsigned b0 = sV[(ks * 8 + tg) * 136 + nt * 8 + g];
                unsigned b1 = sV[(ks * 8 + tg + 4) * 136 + nt * 8 + g];
                mma_tf32(oacc[nt], a0, a1, a2, a3, b0, b1);
            }
        }
        __syncthreads();
    }

    float inv0 = 1.0f / l0, inv1 = 1.0f / l1;
    int b = bh >> 4, h = bh & 15;
    int srow = qt * 128 + qrow + g;
    float* op0 = g_attn + (((size_t)b * SS + srow) * HH + h) * DHD;
    float* op1 = op0 + (size_t)8 * HH * DHD;
    // outputs written RNA-tf32-rounded: gemm_nt (tf32 mma) then sees exact operands
#pragma unroll
    for (int nt = 0; nt < 16; nt++) {
        int cc = nt * 8 + 2 * tg;
        *(float2*)(op0 + cc) = make_float2(__uint_as_float(f2tf(oacc[nt][0] * inv0)),
                                           __uint_as_float(f2tf(oacc[nt][1] * inv0)));
        *(float2*)(op1 + cc) = make_float2(__uint_as_float(f2tf(oacc[nt][2] * inv1)),
                                           __uint_as_float(f2tf(oacc[nt][3] * inv1)));
    }
}

// ---------------- launcher ----------------
extern "C" void kernel_launch(void* const* d_in, const int* in_sizes, int n_in,
                              void* d_out, int out_size) {
    const float* hidden = (const float*)d_in[0];
    const float* cosb   = (const float*)d_in[1];
    const float* sinb   = (const float*)d_in[2];
    const float* wqkv   = (const float*)d_in[3];
    const float* wo     = (const float*)d_in[4];

    float *qkv = nullptr, *attn = nullptr, *hid_r = nullptr, *wqkv_r = nullptr, *wo_r = nullptr;
    cudaGetSymbolAddress((void**)&qkv, g_qkv);
    cudaGetSymbolAddress((void**)&attn, g_attn);
    cudaGetSymbolAddress((void**)&hid_r, g_hid_r);
    cudaGetSymbolAddress((void**)&wqkv_r, g_wqkv_r);
    cudaGetSymbolAddress((void**)&wo_r, g_wo_r);
    cudaFuncSetAttribute(flash_kernel, cudaFuncAttributeMaxDynamicSharedMemorySize, FA_SMEM_BYTES);
    cudaFuncSetAttribute(gemm_nt, cudaFuncAttributeMaxDynamicSharedMemorySize, GEMM_SMEM);

    // 0) RNA-tf32 pre-round of GEMM operands (exact grids: n/4/256 blocks)
    round_tf32_kernel<<<8192, 256>>>((const float4*)hidden, (float4*)hid_r);     // 8.4M elems
    round_tf32_kernel<<<12288, 256>>>((const float4*)wqkv, (float4*)wqkv_r);     // 12.6M
    round_tf32_kernel<<<4096, 256>>>((const float4*)wo, (float4*)wo_r);          // 4.2M

    // 1) QKV projection: [4096,2048] x [6144,2048]^T
    gemm_nt<<<dim3(NQKV / 128, (BB * SS) / 128), 256, GEMM_SMEM>>>(hid_r, wqkv_r, qkv, BB * SS, NQKV, HIDD);

    // 2) RoPE + split + transpose (12,582,912 pairs = 49152 * 256 exactly)
    rope_split_kernel<<<49152, 256>>>(cosb, sinb);

    // 3) Attention (writes tf32-rounded attn)
    flash_kernel<<<dim3(SS / 128, BB * HH), 256, FA_SMEM_BYTES>>>();

    // 4) Output projection: [4096,2048] x [2048,2048]^T -> d_out
    gemm_nt<<<dim3(HIDD / 128, (BB * SS) / 128), 256, GEMM_SMEM>>>(attn, wo_r, (float*)d_out, BB * SS, HIDD, HIDD);
}

// round 9
// speedup vs baseline: 1.2222x; 1.2222x over previous
#include <cuda_runtime.h>
#include <cuda_bf16.h>
#include <math.h>

#define BB 2
#define SS 2048
#define HH 16
#define DHD 128
#define HIDD 2048
#define NQKV 6144   // (H + 2*HKV) * DH

// ---------------- scratch (static device allocations — allowed) ----------------
__device__ float g_qkv[(size_t)BB * SS * NQKV];         // [4096, 6144]
__device__ float g_q[(size_t)BB * HH * SS * DHD];       // [bh, s, d] (pre-scaled by 1/sqrt(DH))
__device__ float g_k[(size_t)BB * HH * SS * DHD];
__device__ float g_v[(size_t)BB * HH * SS * DHD];
__device__ float g_attn[(size_t)BB * SS * HH * DHD];    // [b, s, h, d] == [4096, 2048]
__device__ float g_hid_r[(size_t)BB * SS * HIDD];       // RNA-tf32-rounded copies
__device__ float g_wqkv_r[(size_t)NQKV * HIDD];
__device__ float g_wo_r[(size_t)HIDD * HIDD];

// ---------------- helpers ----------------
__device__ __forceinline__ unsigned f2tf(float f) {
    unsigned u;
    asm("cvt.rna.tf32.f32 %0, %1;" : "=r"(u) : "f"(f));
    return u;
}

__device__ __forceinline__ unsigned smem_u32(const void* p) {
    unsigned a;
    asm("{ .reg .u64 t; cvta.to.shared.u64 t, %1; cvt.u32.u64 %0, t; }" : "=r"(a) : "l"(p));
    return a;
}

__device__ __forceinline__ void cp16(unsigned dst, const void* src) {
    asm volatile("cp.async.cg.shared.global [%0], [%1], 16;\n" :: "r"(dst), "l"(src));
}

__device__ __forceinline__ void mma_tf32(float (&c)[4],
                                         unsigned a0, unsigned a1, unsigned a2, unsigned a3,
                                         unsigned b0, unsigned b1) {
    asm volatile(
        "mma.sync.aligned.m16n8k8.row.col.f32.tf32.tf32.f32 "
        "{%0,%1,%2,%3},{%4,%5,%6,%7},{%8,%9},{%0,%1,%2,%3};\n"
        : "+f"(c[0]), "+f"(c[1]), "+f"(c[2]), "+f"(c[3])
        : "r"(a0), "r"(a1), "r"(a2), "r"(a3), "r"(b0), "r"(b1));
}

// ---------------- GEMM: C[M,N] = A[M,K] * B[N,K]^T (both row-major, K-contig) ------------
// Block 128x128, 4 warps (2x2), warp tile 64x64 (LDS/MMA = 1.0), BK=32,
// 3-stage cp.async pipeline (36KB/stage, 108KB/CTA, 2 CTAs/SM via 128 threads).
// Row stride 36 words (32 data + 4 pad): banks (36g+tg)%32 = (4g+tg)%32 cover all
// 32 banks => conflict-free scalar LDS for every fragment pattern.
// Fragment double-buffering: k-step ks+1 fragments load while ks MMAs issue.
// Inputs MUST be pre-rounded to RNA-tf32 (f32 bit pattern == tf32 operand format).
#define NSTG 3
#define SRD 36
#define STW (256 * SRD)                    // words per stage (A 128 rows + B 128 rows)
#define GEMM_SMEM (NSTG * STW * 4)         // 110592 bytes

__global__ __launch_bounds__(128, 2) void gemm_nt(const float* __restrict__ A,
                                                  const float* __restrict__ Bm,
                                                  float* __restrict__ C,
                                                  int M, int N, int K) {
    extern __shared__ float sm[];
    const unsigned smb = smem_u32(sm);
    const int tid = threadIdx.x;
    const int lane = tid & 31;
    const int w = tid >> 5;
    const int g = lane >> 2;
    const int tg = lane & 3;
    const int wrow = (w >> 1) * 64;
    const int wcol = (w & 1) * 64;
    const int bm = blockIdx.y * 128;
    const int bn = blockIdx.x * 128;
    const int nk = K >> 5;                 // BK=32 tiles

    float acc[4][8][4];
#pragma unroll
    for (int i = 0; i < 4; i++)
#pragma unroll
        for (int j = 0; j < 8; j++)
#pragma unroll
            for (int l = 0; l < 4; l++) acc[i][j][l] = 0.f;

    // loader: per ktile 2048 x 16B chunks (A 128 rows + B 128 rows, 8 chunks/row);
    // 16 cp16 per thread.
    const int lr = tid >> 3;               // row 0..15 step -> covers 128 via +16*i? no:
    // id = tid + 128*i, r = id>>3 in 0..127, ch = id&7
#define FILL(slot, ktv)                                                                     \
    {                                                                                       \
        const unsigned stA = smb + (slot) * (STW * 4);                                      \
        const unsigned stB = stA + 128 * SRD * 4;                                           \
        const int kof = (ktv) * 32;                                                         \
        _Pragma("unroll")                                                                   \
        for (int i = 0; i < 8; i++) {                                                       \
            int id = tid + 128 * i;                                                         \
            int r = id >> 3, ch = id & 7;                                                   \
            cp16(stA + (r * SRD + ch * 4) * 4, A + (size_t)(bm + r) * K + kof + ch * 4);    \
            cp16(stB + (r * SRD + ch * 4) * 4, Bm + (size_t)(bn + r) * K + kof + ch * 4);   \
        }                                                                                   \
        asm volatile("cp.async.commit_group;" ::: "memory");                                \
    }

    FILL(0, 0)
    FILL(1, 1)

    for (int kt = 0; kt < nk; kt++) {
        asm volatile("cp.async.wait_group 1;" ::: "memory");
        __syncthreads();
        const int pf = kt + 2;
        if (pf < nk) {
            FILL(pf % 3, pf)               // slot (kt-1)%3: consumed, all warps past barrier
        } else {
            asm volatile("cp.async.commit_group;" ::: "memory");  // keep group count aligned
        }

        const float* sa = sm + (kt % 3) * STW;
        const float* sb = sa + 128 * SRD;

        // fragment double buffer: af[p][mt][4], bf[p][nt][2]
        unsigned af[2][4][4], bf[2][8][2];
#define LOAD_FRAGS(p, ks)                                                        \
        {                                                                        \
            const int ko = (ks) * 8 + tg;                                        \
            _Pragma("unroll")                                                    \
            for (int mt = 0; mt < 4; mt++) {                                     \
                int r0 = wrow + mt * 16 + g;                                     \
                af[p][mt][0] = __float_as_uint(sa[r0 * SRD + ko]);               \
                af[p][mt][1] = __float_as_uint(sa[(r0 + 8) * SRD + ko]);         \
                af[p][mt][2] = __float_as_uint(sa[r0 * SRD + ko + 4]);           \
                af[p][mt][3] = __float_as_uint(sa[(r0 + 8) * SRD + ko + 4]);     \
            }                                                                    \
            _Pragma("unroll")                                                    \
            for (int nt = 0; nt < 8; nt++) {                                     \
                int rn = wcol + nt * 8 + g;                                      \
                bf[p][nt][0] = __float_as_uint(sb[rn * SRD + ko]);               \
                bf[p][nt][1] = __float_as_uint(sb[rn * SRD + ko + 4]);           \
            }                                                                    \
        }

        LOAD_FRAGS(0, 0)
#pragma unroll
        for (int ks = 0; ks < 4; ks++) {
            const int cb = ks & 1;
            if (ks < 3) LOAD_FRAGS(cb ^ 1, ks + 1)
#pragma unroll
            for (int mt = 0; mt < 4; mt++)
#pragma unroll
                for (int nt = 0; nt < 8; nt++)
                    mma_tf32(acc[mt][nt], af[cb][mt][0], af[cb][mt][1], af[cb][mt][2],
                             af[cb][mt][3], bf[cb][nt][0], bf[cb][nt][1]);
        }
#undef LOAD_FRAGS
    }

#pragma unroll
    for (int mt = 0; mt < 4; mt++) {
        int rr = bm + wrow + mt * 16 + g;
#pragma unroll
        for (int nt = 0; nt < 8; nt++) {
            int cc = bn + wcol + nt * 8 + 2 * tg;
            *(float2*)&C[(size_t)rr * N + cc] = make_float2(acc[mt][nt][0], acc[mt][nt][1]);
            *(float2*)&C[(size_t)(rr + 8) * N + cc] = make_float2(acc[mt][nt][2], acc[mt][nt][3]);
        }
    }
#undef FILL
}

// ---------------- RNA-tf32 pre-round (elementwise) ----------------
__global__ void round_tf32_kernel(const float4* __restrict__ in, float4* __restrict__ out) {
    int i = blockIdx.x * blockDim.x + threadIdx.x;
    float4 v = in[i];
    v.x = __uint_as_float(f2tf(v.x));
    v.y = __uint_as_float(f2tf(v.y));
    v.z = __uint_as_float(f2tf(v.z));
    v.w = __uint_as_float(f2tf(v.w));
    out[i] = v;
}

// ---------------- RoPE + split + transpose to head-major ----------------
__global__ void rope_split_kernel(const float* __restrict__ cosb, const float* __restrict__ sinb) {
    int idx = blockIdx.x * blockDim.x + threadIdx.x;  // pair index, exact grid
    int m = idx / 3072;
    int p = idx - m * 3072;
    int o = p * 2;
    int head = o >> 7;
    int d = o & 127;
    int b = m >> 11;
    int s = m & 2047;
    float2 x = *(const float2*)(g_qkv + (size_t)m * NQKV + o);
    if (head < 2 * HH) {
        float c = cosb[s * DHD + d];
        float sn = sinb[s * DHD + d];
        float y0 = x.x * c - x.y * sn;
        float y1 = x.y * c + x.x * sn;
        if (head < HH) {
            const float sc = 0.08838834764831845f;  // 1/sqrt(128)
            float* dst = g_q + (((size_t)(b * HH + head)) * SS + s) * DHD + d;
            *(float2*)dst = make_float2(y0 * sc, y1 * sc);
        } else {
            float* dst = g_k + (((size_t)(b * HH + head - HH)) * SS + s) * DHD + d;
            *(float2*)dst = make_float2(y0, y1);
        }
    } else {
        float* dst = g_v + (((size_t)(b * HH + head - 2 * HH)) * SS + s) * DHD + d;
        *(float2*)dst = x;
    }
}

// ---------------- Flash attention (legacy mma path) ----------------
// Grid: (S/128, B*H). 256 threads = 8 warps, each warp owns 16 q-rows.
#define FA_SMEM_BYTES 171008

__global__ __launch_bounds__(256, 1) void flash_kernel() {
    extern __shared__ unsigned fsm[];
    unsigned* sQ = fsm;                // 128*132 = 16896
    unsigned* sK = fsm + 16896;        // 64*132  =  8448
    unsigned* sV = fsm + 25344;        // 64*136  =  8704
    unsigned* sP = fsm + 34048;        // 128*68  =  8704

    const int tid = threadIdx.x;
    const int lane = tid & 31;
    const int w = tid >> 5;
    const int g = lane >> 2;
    const int tg = lane & 3;
    const int qt = blockIdx.x;
    const int bh = blockIdx.y;
    const int qrow = w * 16;

    const float* qp = g_q + ((size_t)bh * SS + qt * 128) * DHD;
#pragma unroll
    for (int i = 0; i < 16; i++) {
        int id = tid + 256 * i;
        int r = id >> 5, c4 = (id & 31) * 4;
        float4 v = *(const float4*)(qp + (size_t)r * DHD + c4);
        unsigned* d = sQ + r * 132 + c4;
        d[0] = f2tf(v.x); d[1] = f2tf(v.y); d[2] = f2tf(v.z); d[3] = f2tf(v.w);
    }

    float m0 = -1e30f, m1 = -1e30f, l0 = 0.f, l1 = 0.f;
    float oacc[16][4];
#pragma unroll
    for (int nt = 0; nt < 16; nt++) { oacc[nt][0] = 0; oacc[nt][1] = 0; oacc[nt][2] = 0; oacc[nt][3] = 0; }

    for (int kt = 0; kt < SS / 64; kt++) {
        const float* kp = g_k + ((size_t)bh * SS + kt * 64) * DHD;
        const float* vp = g_v + ((size_t)bh * SS + kt * 64) * DHD;
#pragma unroll
        for (int i = 0; i < 8; i++) {
            int id = tid + 256 * i;
            int r = id >> 5, c4 = (id & 31) * 4;
            float4 kv = *(const float4*)(kp + (size_t)r * DHD + c4);
            unsigned* dk = sK + r * 132 + c4;
            dk[0] = f2tf(kv.x); dk[1] = f2tf(kv.y); dk[2] = f2tf(kv.z); dk[3] = f2tf(kv.w);
            float4 vv = *(const float4*)(vp + (size_t)r * DHD + c4);
            unsigned* dv = sV + r * 136 + c4;
            dv[0] = f2tf(vv.x); dv[1] = f2tf(vv.y); dv[2] = f2tf(vv.z); dv[3] = f2tf(vv.w);
        }
        __syncthreads();

        // S = Q K^T  (scale already folded into Q)
        float sacc[8][4];
#pragma unroll
        for (int nt = 0; nt < 8; nt++) { sacc[nt][0] = 0; sacc[nt][1] = 0; sacc[nt][2] = 0; sacc[nt][3] = 0; }
#pragma unroll
        for (int ks = 0; ks < 16; ks++) {
            unsigned a0 = sQ[(qrow + g) * 132 + ks * 8 + tg];
            unsigned a1 = sQ[(qrow + g + 8) * 132 + ks * 8 + tg];
            unsigned a2 = sQ[(qrow + g) * 132 + ks * 8 + tg + 4];
            unsigned a3 = sQ[(qrow + g + 8) * 132 + ks * 8 + tg + 4];
#pragma unroll
            for (int nt = 0; nt < 8; nt++) {
                unsigned b0 = sK[(nt * 8 + g) * 132 + ks * 8 + tg];
                unsigned b1 = sK[(nt * 8 + g) * 132 + ks * 8 + tg + 4];
                mma_tf32(sacc[nt], a0, a1, a2, a3, b0, b1);
            }
        }

        // online softmax (rows g and g+8 of this warp's 16)
        float mx0 = sacc[0][0], mx1 = sacc[0][2];
#pragma unroll
        for (int nt = 0; nt < 8; nt++) {
            mx0 = fmaxf(mx0, fmaxf(sacc[nt][0], sacc[nt][1]));
            mx1 = fmaxf(mx1, fmaxf(sacc[nt][2], sacc[nt][3]));
        }
        mx0 = fmaxf(mx0, __shfl_xor_sync(0xffffffffu, mx0, 1));
        mx0 = fmaxf(mx0, __shfl_xor_sync(0xffffffffu, mx0, 2));
        mx1 = fmaxf(mx1, __shfl_xor_sync(0xffffffffu, mx1, 1));
        mx1 = fmaxf(mx1, __shfl_xor_sync(0xffffffffu, mx1, 2));
        float nm0 = fmaxf(m0, mx0), nm1 = fmaxf(m1, mx1);
        float al0 = __expf(m0 - nm0), al1 = __expf(m1 - nm1);
        float sum0 = 0.f, sum1 = 0.f;
        unsigned* pr0 = sP + (qrow + g) * 68;
        unsigned* pr1 = sP + (qrow + g + 8) * 68;
#pragma unroll
        for (int nt = 0; nt < 8; nt++) {
            int cc = nt * 8 + 2 * tg;
            unsigned u00 = f2tf(__expf(sacc[nt][0] - nm0));
            unsigned u01 = f2tf(__expf(sacc[nt][1] - nm0));
            unsigned u10 = f2tf(__expf(sacc[nt][2] - nm1));
            unsigned u11 = f2tf(__expf(sacc[nt][3] - nm1));
            sum0 += __uint_as_float(u00) + __uint_as_float(u01);  // sum the tf32-rounded P
            sum1 += __uint_as_float(u10) + __uint_as_float(u11);
            pr0[cc] = u00; pr0[cc + 1] = u01;
            pr1[cc] = u10; pr1[cc + 1] = u11;
        }
        sum0 += __shfl_xor_sync(0xffffffffu, sum0, 1);
        sum0 += __shfl_xor_sync(0xffffffffu, sum0, 2);
        sum1 += __shfl_xor_sync(0xffffffffu, sum1, 1);
        sum1 += __shfl_xor_sync(0xffffffffu, sum1, 2);
        l0 = l0 * al0 + sum0;
        l1 = l1 * al1 + sum1;
        m0 = nm0; m1 = nm1;
#pragma unroll
        for (int nt = 0; nt < 16; nt++) {
            oacc[nt][0] *= al0; oacc[nt][1] *= al0;
            oacc[nt][2] *= al1; oacc[nt][3] *= al1;
        }
        __syncwarp();

        // O += P V   (P is A-operand via smem, V is B-operand)
#pragma unroll
        for (int ks = 0; ks < 8; ks++) {
            unsigned a0 = sP[(qrow + g) * 68 + ks * 8 + tg];
            unsigned a1 = sP[(qrow + g + 8) * 68 + ks * 8 + tg];
            unsigned a2 = sP[(qrow + g) * 68 + ks * 8 + tg + 4];
            unsigned a3 = sP[(qrow + g + 8) * 68 + ks * 8 + tg + 4];
#pragma unroll
            for (int nt = 0; nt < 16; nt++) {
                unsigned b0 = sV[(ks * 8 + tg) * 136 + nt * 8 + g];
                unsigned b1 = sV[(ks * 8 + tg + 4) * 136 + nt * 8 + g];
                mma_tf32(oacc[nt], a0, a1, a2, a3, b0, b1);
            }
        }
        __syncthreads();
    }

    float inv0 = 1.0f / l0, inv1 = 1.0f / l1;
    int b = bh >> 4, h = bh & 15;
    int srow = qt * 128 + qrow + g;
    float* op0 = g_attn + (((size_t)b * SS + srow) * HH + h) * DHD;
    float* op1 = op0 + (size_t)8 * HH * DHD;
    // outputs written RNA-tf32-rounded: gemm_nt (tf32 mma) then sees exact operands
#pragma unroll
    for (int nt = 0; nt < 16; nt++) {
        int cc = nt * 8 + 2 * tg;
        *(float2*)(op0 + cc) = make_float2(__uint_as_float(f2tf(oacc[nt][0] * inv0)),
                                           __uint_as_float(f2tf(oacc[nt][1] * inv0)));
        *(float2*)(op1 + cc) = make_float2(__uint_as_float(f2tf(oacc[nt][2] * inv1)),
                                           __uint_as_float(f2tf(oacc[nt][3] * inv1)));
    }
}

// ---------------- launcher ----------------
extern "C" void kernel_launch(void* const* d_in, const int* in_sizes, int n_in,
                              void* d_out, int out_size) {
    const float* hidden = (const float*)d_in[0];
    const float* cosb   = (const float*)d_in[1];
    const float* sinb   = (const float*)d_in[2];
    const float* wqkv   = (const float*)d_in[3];
    const float* wo     = (const float*)d_in[4];

    float *qkv = nullptr, *attn = nullptr, *hid_r = nullptr, *wqkv_r = nullptr, *wo_r = nullptr;
    cudaGetSymbolAddress((void**)&qkv, g_qkv);
    cudaGetSymbolAddress((void**)&attn, g_attn);
    cudaGetSymbolAddress((void**)&hid_r, g_hid_r);
    cudaGetSymbolAddress((void**)&wqkv_r, g_wqkv_r);
    cudaGetSymbolAddress((void**)&wo_r, g_wo_r);
    cudaFuncSetAttribute(flash_kernel, cudaFuncAttributeMaxDynamicSharedMemorySize, FA_SMEM_BYTES);
    cudaFuncSetAttribute(gemm_nt, cudaFuncAttributeMaxDynamicSharedMemorySize, GEMM_SMEM);

    // 0) RNA-tf32 pre-round of GEMM operands (exact grids: n/4/256 blocks)
    round_tf32_kernel<<<8192, 256>>>((const float4*)hidden, (float4*)hid_r);     // 8.4M elems
    round_tf32_kernel<<<12288, 256>>>((const float4*)wqkv, (float4*)wqkv_r);     // 12.6M
    round_tf32_kernel<<<4096, 256>>>((const float4*)wo, (float4*)wo_r);          // 4.2M

    // 1) QKV projection: [4096,2048] x [6144,2048]^T
    gemm_nt<<<dim3(NQKV / 128, (BB * SS) / 128), 128, GEMM_SMEM>>>(hid_r, wqkv_r, qkv, BB * SS, NQKV, HIDD);

    // 2) RoPE + split + transpose (12,582,912 pairs = 49152 * 256 exactly)
    rope_split_kernel<<<49152, 256>>>(cosb, sinb);

    // 3) Attention (writes tf32-rounded attn)
    flash_kernel<<<dim3(SS / 128, BB * HH), 256, FA_SMEM_BYTES>>>();

    // 4) Output projection: [4096,2048] x [2048,2048]^T -> d_out
    gemm_nt<<<dim3(HIDD / 128, (BB * SS) / 128), 128, GEMM_SMEM>>>(attn, wo_r, (float*)d_out, BB * SS, HIDD, HIDD);
}